// round 8
// baseline (speedup 1.0000x reference)
#include <cuda_runtime.h>
#include <cstdint>

// ---------------------------------------------------------------------------
// SelfAttention: out = softmax((xWq^T+bq)(xWk^T+bk)^T / sqrt(D)) (xWv^T+bv)
// B=4, S=2048, D=1024. fp32 I/O.
// Round 7: exact R3 structure (best: 837.9us) — 128 threads, 4 warps of 64x64,
// 2-stage cp.async, separate QKV GEMMs with V stored transposed directly —
// plus ONE change: single __syncthreads per mainloop iteration
// (wait -> bar -> issue-next-loads -> compute; trailing bar proved redundant).
// TF32 mma.sync, operands pre-rounded in gmem.
// ---------------------------------------------------------------------------

#define DEV_INLINE __device__ __forceinline__

static constexpr int Bsz = 4;
static constexpr int S   = 2048;
static constexpr int D   = 1024;
static constexpr int MQK = Bsz * S;

// Scratch (static __device__ arrays: allocation-free per harness rules)
__device__ float g_q [(size_t)MQK * D];
__device__ float g_k [(size_t)MQK * D];
__device__ float g_vT[(size_t)Bsz * D * S];   // V stored transposed per batch
__device__ float g_s [(size_t)Bsz * S * S];   // scores; prologue aliases
                                              // rounded x / W copies here

DEV_INLINE float tf32_round(float x) {
    uint32_t u;
    asm("cvt.rna.tf32.f32 %0, %1;" : "=r"(u) : "f"(x));
    return __uint_as_float(u);
}

DEV_INLINE uint32_t smem_u32(const void* p) {
    uint32_t a;
    asm("{ .reg .u64 t; cvta.to.shared.u64 t, %1; cvt.u32.u64 %0, t; }"
        : "=r"(a) : "l"(p));
    return a;
}

DEV_INLINE void cp_async16(uint32_t dst, const void* src) {
    asm volatile("cp.async.cg.shared.global [%0], [%1], 16;"
                 :: "r"(dst), "l"(src) : "memory");
}
DEV_INLINE void cp_commit() {
    asm volatile("cp.async.commit_group;" ::: "memory");
}
template <int N> DEV_INLINE void cp_wait() {
    asm volatile("cp.async.wait_group %0;" :: "n"(N) : "memory");
}

DEV_INLINE void mma_16x8x8(float acc[4], const uint32_t a[4], const uint32_t b[2]) {
    asm volatile(
        "mma.sync.aligned.m16n8k8.row.col.f32.tf32.tf32.f32 "
        "{%0,%1,%2,%3}, {%4,%5,%6,%7}, {%8,%9}, {%0,%1,%2,%3};\n"
        : "+f"(acc[0]), "+f"(acc[1]), "+f"(acc[2]), "+f"(acc[3])
        : "r"(a[0]), "r"(a[1]), "r"(a[2]), "r"(a[3]),
          "r"(b[0]), "r"(b[1]));
}

// ---------------------------------------------------------------------------
// prep_kernel: one launch rounds x and all three weights into gmem scratch.
//   blocks [0, 8192)          : xr = tf32_round(x)
//   blocks [8192, 8192+3072)  : wr[w] = tf32_round(W[w])  (contiguous Wq|Wk|Wv)
// ---------------------------------------------------------------------------
static constexpr int PREP_XB = MQK * D / 4 / 256;        // 8192
static constexpr int PREP_WB = D * D / 4 / 256;          // 1024
static constexpr int PREP_BLOCKS = PREP_XB + 3 * PREP_WB;

__global__ void __launch_bounds__(256)
prep_kernel(const float* __restrict__ x,
            const float* __restrict__ Wq, const float* __restrict__ Wk,
            const float* __restrict__ Wv,
            float* __restrict__ xr, float* __restrict__ wr)
{
    const int b = blockIdx.x;
    const int t = threadIdx.x;
    if (b < PREP_XB) {
        const int i = b * 256 + t;
        float4 v = reinterpret_cast<const float4*>(x)[i];
        v.x = tf32_round(v.x); v.y = tf32_round(v.y);
        v.z = tf32_round(v.z); v.w = tf32_round(v.w);
        reinterpret_cast<float4*>(xr)[i] = v;
    } else {
        const int wi = b - PREP_XB;
        const int w  = wi >> 10;                 // 0,1,2
        const int i  = (wi & 1023) * 256 + t;
        const float* src = (w == 0) ? Wq : (w == 1) ? Wk : Wv;
        float* dst = wr + (size_t)w * D * D;
        float4 v = reinterpret_cast<const float4*>(src)[i];
        v.x = tf32_round(v.x); v.y = tf32_round(v.y);
        v.z = tf32_round(v.z); v.w = tf32_round(v.w);
        reinterpret_cast<float4*>(dst)[i] = v;
    }
}

// ---------------------------------------------------------------------------
// TF32 NT GEMM: C[m,n] = alpha * sum_k A[m,k]*B[n,k]  (+bias[n])
// A: [M,K] row-major, B: [N,K] row-major, both ALREADY tf32-valued in gmem.
// CTA 128x128x(BK=32), 128 threads = 4 warps of 64x64.
// 2-stage cp.async, SINGLE __syncthreads per iteration:
//   iter i: cp_wait<0>; bar; issue loads for stage i+1; compute stage i.
// Safety: loads issued after the bar write buf (i+1)&1, which every warp last
// read during compute(i-1) — completed before this bar in its program order.
// STORE_T: store C transposed (C[n][m]).  ROUND_OUT: tf32-round before store.
// ---------------------------------------------------------------------------
static constexpr int BM = 128, BN = 128, BK = 32;
static constexpr int ROWF  = BK + 4;             // 36 floats/row (16B-aligned)
static constexpr int STG   = BM * ROWF;          // floats per operand stage
static constexpr int DYN_SMEM = 4 * STG * 4;     // 2 stages x (A+B) = 73728 B

template <bool STORE_T, bool ROUND_OUT>
__global__ void __launch_bounds__(128)
gemm_mma_kernel(const float* __restrict__ A, int lda, long long strideA,
                const float* __restrict__ B, int ldb, long long strideB,
                float* __restrict__ C, int ldc, long long strideC,
                const float* __restrict__ bias, int K, float alpha)
{
    extern __shared__ float dyn[];
    float* As = dyn;                 // [2][STG]
    float* Bs = dyn + 2 * STG;       // [2][STG]
    const uint32_t sA = smem_u32(As);
    const uint32_t sB = smem_u32(Bs);

    const int tid  = threadIdx.x;
    const int wid  = tid >> 5;
    const int lane = tid & 31;
    const int m_w  = (wid & 1) * 64;          // 2 warps along M
    const int n_w  = (wid >> 1) * 64;         // 2 warps along N
    const int group = lane >> 2;              // 0..7
    const int tig   = lane & 3;               // 0..3

    const int bz = blockIdx.z;
    A += (size_t)bz * strideA;
    B += (size_t)bz * strideB;
    C += (size_t)bz * strideC;
    const int bm = blockIdx.y * BM;
    const int bn = blockIdx.x * BN;

    float acc[4][8][4];
    #pragma unroll
    for (int mi = 0; mi < 4; mi++)
        #pragma unroll
        for (int ni = 0; ni < 8; ni++)
            #pragma unroll
            for (int r = 0; r < 4; r++) acc[mi][ni][r] = 0.0f;

    // loader: 8 float4 per operand per thread (128 rows x 8 float4-cols)
    const int lr = tid >> 3;           // base row 0..15
    const int lc = tid & 7;            // float4 col 0..7
    auto load_stage = [&](int s, int k0) {
        const uint32_t offA = sA + (uint32_t)s * STG * 4;
        const uint32_t offB = sB + (uint32_t)s * STG * 4;
        #pragma unroll
        for (int i = 0; i < 8; i++) {
            const int r = lr + 16 * i;
            cp_async16(offA + (uint32_t)(r * ROWF + lc * 4) * 4,
                       &A[(size_t)(bm + r) * lda + k0 + lc * 4]);
        }
        #pragma unroll
        for (int i = 0; i < 8; i++) {
            const int r = lr + 16 * i;
            cp_async16(offB + (uint32_t)(r * ROWF + lc * 4) * 4,
                       &B[(size_t)(bn + r) * ldb + k0 + lc * 4]);
        }
        cp_commit();
    };

    const int nst = K / BK;
    load_stage(0, 0);

    for (int i = 0; i < nst; i++) {
        cp_wait<0>();
        __syncthreads();

        if (i + 1 < nst)
            load_stage((i + 1) & 1, (i + 1) * BK);

        const float* as = As + (i & 1) * STG;
        const float* bs = Bs + (i & 1) * STG;

        #pragma unroll
        for (int ks = 0; ks < BK; ks += 8) {
            uint32_t afr[4][4];
            #pragma unroll
            for (int mi = 0; mi < 4; mi++) {
                const int r = m_w + mi * 16;
                afr[mi][0] = __float_as_uint(as[(r + group    ) * ROWF + ks + tig    ]);
                afr[mi][1] = __float_as_uint(as[(r + group + 8) * ROWF + ks + tig    ]);
                afr[mi][2] = __float_as_uint(as[(r + group    ) * ROWF + ks + tig + 4]);
                afr[mi][3] = __float_as_uint(as[(r + group + 8) * ROWF + ks + tig + 4]);
            }
            uint32_t bfr[8][2];
            #pragma unroll
            for (int ni = 0; ni < 8; ni++) {
                const int c = n_w + ni * 8;
                bfr[ni][0] = __float_as_uint(bs[(c + group) * ROWF + ks + tig    ]);
                bfr[ni][1] = __float_as_uint(bs[(c + group) * ROWF + ks + tig + 4]);
            }
            #pragma unroll
            for (int mi = 0; mi < 4; mi++)
                #pragma unroll
                for (int ni = 0; ni < 8; ni++)
                    mma_16x8x8(acc[mi][ni], afr[mi], bfr[ni]);
        }
    }

    // ---- epilogue ----
    #pragma unroll
    for (int mi = 0; mi < 4; mi++) {
        const int row0 = bm + m_w + mi * 16 + group;
        #pragma unroll
        for (int ni = 0; ni < 8; ni++) {
            const int col0 = bn + n_w + ni * 8 + tig * 2;
            float v00 = acc[mi][ni][0] * alpha;
            float v01 = acc[mi][ni][1] * alpha;
            float v10 = acc[mi][ni][2] * alpha;
            float v11 = acc[mi][ni][3] * alpha;
            if (bias) {
                const float b0 = bias[col0], b1 = bias[col0 + 1];
                v00 += b0; v01 += b1; v10 += b0; v11 += b1;
            }
            if (ROUND_OUT) {
                v00 = tf32_round(v00); v01 = tf32_round(v01);
                v10 = tf32_round(v10); v11 = tf32_round(v11);
            }
            if (!STORE_T) {
                *reinterpret_cast<float2*>(&C[(size_t)row0 * ldc + col0]) =
                    make_float2(v00, v01);
                *reinterpret_cast<float2*>(&C[(size_t)(row0 + 8) * ldc + col0]) =
                    make_float2(v10, v11);
            } else {
                C[(size_t)col0 * ldc + row0]           = v00;
                C[(size_t)(col0 + 1) * ldc + row0]     = v01;
                C[(size_t)col0 * ldc + row0 + 8]       = v10;
                C[(size_t)(col0 + 1) * ldc + row0 + 8] = v11;
            }
        }
    }
}

// ---------------------------------------------------------------------------
// Row softmax, in place, tf32-rounded output. One block (256 threads) per row.
// float4 I/O (2 float4 per thread per row of 2048).
// ---------------------------------------------------------------------------
__global__ void __launch_bounds__(256)
softmax_kernel(float* __restrict__ Smat, int ncols)
{
    float4* p = reinterpret_cast<float4*>(Smat + (size_t)blockIdx.x * ncols);
    const int tid  = threadIdx.x;
    const int warp = tid >> 5;
    const int lane = tid & 31;

    __shared__ float red_max[8];
    __shared__ float red_sum[8];

    float4 v[2];
    float mx = -1e30f;
    #pragma unroll
    for (int i = 0; i < 2; i++) {
        v[i] = p[tid + 256 * i];
        mx = fmaxf(fmaxf(fmaxf(mx, v[i].x), fmaxf(v[i].y, v[i].z)), v[i].w);
    }
    #pragma unroll
    for (int o = 16; o > 0; o >>= 1)
        mx = fmaxf(mx, __shfl_xor_sync(0xffffffffu, mx, o));
    if (lane == 0) red_max[warp] = mx;
    __syncthreads();
    float m = red_max[0];
    #pragma unroll
    for (int w = 1; w < 8; w++) m = fmaxf(m, red_max[w]);

    float sum = 0.f;
    #pragma unroll
    for (int i = 0; i < 2; i++) {
        v[i].x = __expf(v[i].x - m); v[i].y = __expf(v[i].y - m);
        v[i].z = __expf(v[i].z - m); v[i].w = __expf(v[i].w - m);
        sum += (v[i].x + v[i].y) + (v[i].z + v[i].w);
    }
    #pragma unroll
    for (int o = 16; o > 0; o >>= 1)
        sum += __shfl_xor_sync(0xffffffffu, sum, o);
    if (lane == 0) red_sum[warp] = sum;
    __syncthreads();
    float total = 0.f;
    #pragma unroll
    for (int w = 0; w < 8; w++) total += red_sum[w];

    const float inv = 1.0f / total;
    #pragma unroll
    for (int i = 0; i < 2; i++) {
        v[i].x = tf32_round(v[i].x * inv);
        v[i].y = tf32_round(v[i].y * inv);
        v[i].z = tf32_round(v[i].z * inv);
        v[i].w = tf32_round(v[i].w * inv);
        p[tid + 256 * i] = v[i];
    }
}

// ---------------------------------------------------------------------------
extern "C" void kernel_launch(void* const* d_in, const int* in_sizes, int n_in,
                              void* d_out, int out_size)
{
    const float* x  = (const float*)d_in[0];
    const float* Wq = (const float*)d_in[1];
    const float* bq = (const float*)d_in[2];
    const float* Wk = (const float*)d_in[3];
    const float* bk = (const float*)d_in[4];
    const float* Wv = (const float*)d_in[5];
    const float* bv = (const float*)d_in[6];
    float* out = (float*)d_out;

    float *gq, *gk, *gvT, *gs;
    cudaGetSymbolAddress((void**)&gq,  g_q);
    cudaGetSymbolAddress((void**)&gk,  g_k);
    cudaGetSymbolAddress((void**)&gvT, g_vT);
    cudaGetSymbolAddress((void**)&gs,  g_s);

    // tf32-rounded copies of x and the weights, aliased into g_s (not yet
    // live; g_s is first written by the scores GEMM, which runs after QKV).
    float* xr  = gs;                                   // 8192*1024
    float* wqr = gs + (size_t)MQK * D;                 // 3*1024*1024 contiguous
    float* wkr = wqr + (size_t)D * D;
    float* wvr = wkr + (size_t)D * D;

    cudaFuncSetAttribute(gemm_mma_kernel<false, true>,
                         cudaFuncAttributeMaxDynamicSharedMemorySize, DYN_SMEM);
    cudaFuncSetAttribute(gemm_mma_kernel<true, true>,
                         cudaFuncAttributeMaxDynamicSharedMemorySize, DYN_SMEM);
    cudaFuncSetAttribute(gemm_mma_kernel<false, false>,
                         cudaFuncAttributeMaxDynamicSharedMemorySize, DYN_SMEM);

    // 0) prep: round x, Wq, Wk, Wv into gmem scratch. One launch.
    prep_kernel<<<PREP_BLOCKS, 256>>>(x, Wq, Wk, Wv, xr, wqr);

    const dim3 blk(128);

    // 1) Q, K projections: [8192,1024] = xr @ W^T + b (NT, rounded output)
    {
        const dim3 grid(D / BN, MQK / BM, 1);
        gemm_mma_kernel<false, true><<<grid, blk, DYN_SMEM>>>(
            xr, D, 0, wqr, D, 0, gq, D, 0, bq, D, 1.0f);
        gemm_mma_kernel<false, true><<<grid, blk, DYN_SMEM>>>(
            xr, D, 0, wkr, D, 0, gk, D, 0, bk, D, 1.0f);
    }
    // 1b) V projection, stored transposed directly: g_vT[b][d][s]
    {
        const dim3 grid(D / BN, S / BM, Bsz);
        gemm_mma_kernel<true, true><<<grid, blk, DYN_SMEM>>>(
            xr,  D, (long long)S * D,
            wvr, D, 0,
            gvT, S, (long long)D * S,
            bv, D, 1.0f);
    }

    // 2) scores[b] = Q[b] @ K[b]^T * (1/sqrt(D))  (overwrites aliased prep data)
    {
        const dim3 grid(S / BN, S / BM, Bsz);
        gemm_mma_kernel<false, false><<<grid, blk, DYN_SMEM>>>(
            gq, D, (long long)S * D,
            gk, D, (long long)S * D,
            gs, S, (long long)S * S,
            nullptr, D, 0.03125f /* 1/sqrt(1024) */);
    }

    // 3) row softmax (tf32-rounded output)
    softmax_kernel<<<Bsz * S, 256>>>(gs, S);

    // 4) out[b] = P[b] @ V[b] = P[b] @ (vT[b])^T  (NT path)
    {
        const dim3 grid(D / BN, S / BM, Bsz);
        gemm_mma_kernel<false, false><<<grid, blk, DYN_SMEM>>>(
            gs,  S, (long long)S * S,
            gvT, S, (long long)D * S,
            out, D, (long long)S * D,
            nullptr, S, 1.0f);
    }
}

// round 10
// speedup vs baseline: 1.0090x; 1.0090x over previous
#include <cuda_runtime.h>
#include <cstdint>

// ---------------------------------------------------------------------------
// SelfAttention: out = softmax((xWq^T+bq)(xWk^T+bk)^T / sqrt(D)) (xWv^T+bv)
// B=4, S=2048, D=1024. fp32 I/O.
// Round 9: R8 design with the batch-offset bug in PV row scaling FIXED
// (rowscale now indexed with a per-batch stride). Mainloop = frozen R3 config.
//   - V projection: smem-staged transposed epilogue (coalesced stores)
//   - scores: exp() fused into epilogue (scores bounded; max-free softmax)
//   - softmax kernel replaced by read-only inv-rowsum reduction
//   - PV: row scaling by inv_rowsum fused into epilogue
// TF32 mma.sync, operands pre-rounded in gmem.
// ---------------------------------------------------------------------------

#define DEV_INLINE __device__ __forceinline__

static constexpr int Bsz = 4;
static constexpr int S   = 2048;
static constexpr int D   = 1024;
static constexpr int MQK = Bsz * S;

// Scratch (static __device__ arrays: allocation-free per harness rules)
__device__ float g_q  [(size_t)MQK * D];
__device__ float g_k  [(size_t)MQK * D];
__device__ float g_vT [(size_t)Bsz * D * S];  // V stored transposed per batch
__device__ float g_s  [(size_t)Bsz * S * S];  // E = exp(scores); prologue
                                              // aliases rounded x / W here
__device__ float g_inv[MQK];                  // 1 / rowsum(E)

DEV_INLINE float tf32_round(float x) {
    uint32_t u;
    asm("cvt.rna.tf32.f32 %0, %1;" : "=r"(u) : "f"(x));
    return __uint_as_float(u);
}

DEV_INLINE uint32_t smem_u32(const void* p) {
    uint32_t a;
    asm("{ .reg .u64 t; cvta.to.shared.u64 t, %1; cvt.u32.u64 %0, t; }"
        : "=r"(a) : "l"(p));
    return a;
}

DEV_INLINE void cp_async16(uint32_t dst, const void* src) {
    asm volatile("cp.async.cg.shared.global [%0], [%1], 16;"
                 :: "r"(dst), "l"(src) : "memory");
}
DEV_INLINE void cp_commit() {
    asm volatile("cp.async.commit_group;" ::: "memory");
}
template <int N> DEV_INLINE void cp_wait() {
    asm volatile("cp.async.wait_group %0;" :: "n"(N) : "memory");
}

DEV_INLINE void mma_16x8x8(float acc[4], const uint32_t a[4], const uint32_t b[2]) {
    asm volatile(
        "mma.sync.aligned.m16n8k8.row.col.f32.tf32.tf32.f32 "
        "{%0,%1,%2,%3}, {%4,%5,%6,%7}, {%8,%9}, {%0,%1,%2,%3};\n"
        : "+f"(acc[0]), "+f"(acc[1]), "+f"(acc[2]), "+f"(acc[3])
        : "r"(a[0]), "r"(a[1]), "r"(a[2]), "r"(a[3]),
          "r"(b[0]), "r"(b[1]));
}

// ---------------------------------------------------------------------------
// prep_kernel: rounds x and all three weights into gmem scratch. One launch.
// ---------------------------------------------------------------------------
static constexpr int PREP_XB = MQK * D / 4 / 256;        // 8192
static constexpr int PREP_WB = D * D / 4 / 256;          // 1024
static constexpr int PREP_BLOCKS = PREP_XB + 3 * PREP_WB;

__global__ void __launch_bounds__(256)
prep_kernel(const float* __restrict__ x,
            const float* __restrict__ Wq, const float* __restrict__ Wk,
            const float* __restrict__ Wv,
            float* __restrict__ xr, float* __restrict__ wr)
{
    const int b = blockIdx.x;
    const int t = threadIdx.x;
    if (b < PREP_XB) {
        const int i = b * 256 + t;
        float4 v = reinterpret_cast<const float4*>(x)[i];
        v.x = tf32_round(v.x); v.y = tf32_round(v.y);
        v.z = tf32_round(v.z); v.w = tf32_round(v.w);
        reinterpret_cast<float4*>(xr)[i] = v;
    } else {
        const int wi = b - PREP_XB;
        const int w  = wi >> 10;                 // 0,1,2
        const int i  = (wi & 1023) * 256 + t;
        const float* src = (w == 0) ? Wq : (w == 1) ? Wk : Wv;
        float* dst = wr + (size_t)w * D * D;
        float4 v = reinterpret_cast<const float4*>(src)[i];
        v.x = tf32_round(v.x); v.y = tf32_round(v.y);
        v.z = tf32_round(v.z); v.w = tf32_round(v.w);
        reinterpret_cast<float4*>(dst)[i] = v;
    }
}

// ---------------------------------------------------------------------------
// TF32 NT GEMM: C[m,n] = alpha * sum_k A[m,k]*B[n,k]  (+bias[n])
// A: [M,K] row-major, B: [N,K] row-major, both ALREADY tf32-valued in gmem.
// CTA 128x128x(BK=32), 128 threads = 4 warps of 64x64.
// Mainloop = frozen R3 config: issue next loads -> cp_wait<1> -> bar ->
// compute -> bar. Epilogue variants:
//   STORE_T  : smem-staged transpose, coalesced stores of C^T
//   ROUND_OUT: tf32-round before store
//   EXP_OUT  : v = exp(acc*alpha)  (max-free softmax numerator)
//   SCALE    : v *= rowscale[bz*rs_stride + row] (deferred softmax normalize)
// ---------------------------------------------------------------------------
static constexpr int BM = 128, BN = 128, BK = 32;
static constexpr int ROWF  = BK + 4;             // 36 floats/row (16B-aligned)
static constexpr int STG   = BM * ROWF;          // floats per operand stage
static constexpr int DYN_SMEM = 4 * STG * 4;     // 2 stages x (A+B) = 73728 B
static constexpr int TPS = 132;                  // transpose stage row stride
// transpose stage needs 128*132*4 = 67584 <= 73728 bytes: fits in DYN_SMEM

template <bool STORE_T, bool ROUND_OUT, bool EXP_OUT, bool SCALE>
__global__ void __launch_bounds__(128)
gemm_mma_kernel(const float* __restrict__ A, int lda, long long strideA,
                const float* __restrict__ B, int ldb, long long strideB,
                float* __restrict__ C, int ldc, long long strideC,
                const float* __restrict__ bias,
                const float* __restrict__ rowscale, int rs_stride,
                int K, float alpha)
{
    extern __shared__ float dyn[];
    float* As = dyn;                 // [2][STG]
    float* Bs = dyn + 2 * STG;       // [2][STG]
    const uint32_t sA = smem_u32(As);
    const uint32_t sB = smem_u32(Bs);

    const int tid  = threadIdx.x;
    const int wid  = tid >> 5;
    const int lane = tid & 31;
    const int m_w  = (wid & 1) * 64;          // 2 warps along M
    const int n_w  = (wid >> 1) * 64;         // 2 warps along N
    const int group = lane >> 2;              // 0..7
    const int tig   = lane & 3;               // 0..3

    const int bz = blockIdx.z;
    A += (size_t)bz * strideA;
    B += (size_t)bz * strideB;
    C += (size_t)bz * strideC;
    if (SCALE) rowscale += (size_t)bz * rs_stride;   // FIX: per-batch offset
    const int bm = blockIdx.y * BM;
    const int bn = blockIdx.x * BN;

    float acc[4][8][4];
    #pragma unroll
    for (int mi = 0; mi < 4; mi++)
        #pragma unroll
        for (int ni = 0; ni < 8; ni++)
            #pragma unroll
            for (int r = 0; r < 4; r++) acc[mi][ni][r] = 0.0f;

    // loader: 8 float4 per operand per thread (128 rows x 8 float4-cols)
    const int lr = tid >> 3;           // base row 0..15
    const int lc = tid & 7;            // float4 col 0..7
    auto load_stage = [&](int s, int k0) {
        const uint32_t offA = sA + (uint32_t)s * STG * 4;
        const uint32_t offB = sB + (uint32_t)s * STG * 4;
        #pragma unroll
        for (int i = 0; i < 8; i++) {
            const int r = lr + 16 * i;
            cp_async16(offA + (uint32_t)(r * ROWF + lc * 4) * 4,
                       &A[(size_t)(bm + r) * lda + k0 + lc * 4]);
        }
        #pragma unroll
        for (int i = 0; i < 8; i++) {
            const int r = lr + 16 * i;
            cp_async16(offB + (uint32_t)(r * ROWF + lc * 4) * 4,
                       &B[(size_t)(bn + r) * ldb + k0 + lc * 4]);
        }
        cp_commit();
    };

    const int nst = K / BK;
    load_stage(0, 0);

    for (int i = 0; i < nst; i++) {
        if (i + 1 < nst) {
            load_stage((i + 1) & 1, (i + 1) * BK);
            cp_wait<1>();
        } else {
            cp_wait<0>();
        }
        __syncthreads();

        const float* as = As + (i & 1) * STG;
        const float* bs = Bs + (i & 1) * STG;

        #pragma unroll
        for (int ks = 0; ks < BK; ks += 8) {
            uint32_t afr[4][4];
            #pragma unroll
            for (int mi = 0; mi < 4; mi++) {
                const int r = m_w + mi * 16;
                afr[mi][0] = __float_as_uint(as[(r + group    ) * ROWF + ks + tig    ]);
                afr[mi][1] = __float_as_uint(as[(r + group + 8) * ROWF + ks + tig    ]);
                afr[mi][2] = __float_as_uint(as[(r + group    ) * ROWF + ks + tig + 4]);
                afr[mi][3] = __float_as_uint(as[(r + group + 8) * ROWF + ks + tig + 4]);
            }
            uint32_t bfr[8][2];
            #pragma unroll
            for (int ni = 0; ni < 8; ni++) {
                const int c = n_w + ni * 8;
                bfr[ni][0] = __float_as_uint(bs[(c + group) * ROWF + ks + tig    ]);
                bfr[ni][1] = __float_as_uint(bs[(c + group) * ROWF + ks + tig + 4]);
            }
            #pragma unroll
            for (int mi = 0; mi < 4; mi++)
                #pragma unroll
                for (int ni = 0; ni < 8; ni++)
                    mma_16x8x8(acc[mi][ni], afr[mi], bfr[ni]);
        }
        __syncthreads();
    }

    // ---- epilogue ----
    float rs[8];
    if (SCALE) {
        #pragma unroll
        for (int mi = 0; mi < 4; mi++) {
            rs[2 * mi]     = rowscale[bm + m_w + mi * 16 + group];
            rs[2 * mi + 1] = rowscale[bm + m_w + mi * 16 + group + 8];
        }
    }

    #pragma unroll
    for (int mi = 0; mi < 4; mi++) {
        const int rloc0 = m_w + mi * 16 + group;
        const int row0  = bm + rloc0;
        #pragma unroll
        for (int ni = 0; ni < 8; ni++) {
            const int cloc0 = n_w + ni * 8 + tig * 2;
            const int col0  = bn + cloc0;
            float v00 = acc[mi][ni][0] * alpha;
            float v01 = acc[mi][ni][1] * alpha;
            float v10 = acc[mi][ni][2] * alpha;
            float v11 = acc[mi][ni][3] * alpha;
            if (bias) {
                const float b0 = bias[col0], b1 = bias[col0 + 1];
                v00 += b0; v01 += b1; v10 += b0; v11 += b1;
            }
            if (EXP_OUT) {
                v00 = __expf(v00); v01 = __expf(v01);
                v10 = __expf(v10); v11 = __expf(v11);
            }
            if (SCALE) {
                v00 *= rs[2 * mi];     v01 *= rs[2 * mi];
                v10 *= rs[2 * mi + 1]; v11 *= rs[2 * mi + 1];
            }
            if (ROUND_OUT) {
                v00 = tf32_round(v00); v01 = tf32_round(v01);
                v10 = tf32_round(v10); v11 = tf32_round(v11);
            }
            if (!STORE_T) {
                *reinterpret_cast<float2*>(&C[(size_t)row0 * ldc + col0]) =
                    make_float2(v00, v01);
                *reinterpret_cast<float2*>(&C[(size_t)(row0 + 8) * ldc + col0]) =
                    make_float2(v10, v11);
            } else {
                // stage into smem transpose buffer: T[c][r], stride TPS
                dyn[(size_t)cloc0 * TPS + rloc0]           = v00;
                dyn[(size_t)(cloc0 + 1) * TPS + rloc0]     = v01;
                dyn[(size_t)cloc0 * TPS + rloc0 + 8]       = v10;
                dyn[(size_t)(cloc0 + 1) * TPS + rloc0 + 8] = v11;
            }
        }
    }

    if (STORE_T) {
        __syncthreads();
        // each warp writes 32 transposed rows, coalesced float4
        #pragma unroll
        for (int j = 0; j < 32; j++) {
            const int dr = wid * 32 + j;
            const float4 v = *reinterpret_cast<const float4*>(
                &dyn[(size_t)dr * TPS + lane * 4]);
            *reinterpret_cast<float4*>(
                &C[(size_t)(bn + dr) * ldc + bm + lane * 4]) = v;
        }
    }
}

// ---------------------------------------------------------------------------
// inv-rowsum reduction: g_inv[row] = 1 / sum(E[row, :]).
// One block (256 threads) per row of 2048 floats. Read-only over E.
// ---------------------------------------------------------------------------
__global__ void __launch_bounds__(256)
rowsum_inv_kernel(const float* __restrict__ E, float* __restrict__ inv, int ncols)
{
    const float4* p = reinterpret_cast<const float4*>(E + (size_t)blockIdx.x * ncols);
    const int tid  = threadIdx.x;
    const int warp = tid >> 5;
    const int lane = tid & 31;

    __shared__ float red[8];

    float sum = 0.f;
    #pragma unroll
    for (int i = 0; i < 2; i++) {
        const float4 v = p[tid + 256 * i];
        sum += (v.x + v.y) + (v.z + v.w);
    }
    #pragma unroll
    for (int o = 16; o > 0; o >>= 1)
        sum += __shfl_xor_sync(0xffffffffu, sum, o);
    if (lane == 0) red[warp] = sum;
    __syncthreads();
    if (tid == 0) {
        float total = 0.f;
        #pragma unroll
        for (int w = 0; w < 8; w++) total += red[w];
        inv[blockIdx.x] = 1.0f / total;
    }
}

// ---------------------------------------------------------------------------
extern "C" void kernel_launch(void* const* d_in, const int* in_sizes, int n_in,
                              void* d_out, int out_size)
{
    const float* x  = (const float*)d_in[0];
    const float* Wq = (const float*)d_in[1];
    const float* bq = (const float*)d_in[2];
    const float* Wk = (const float*)d_in[3];
    const float* bk = (const float*)d_in[4];
    const float* Wv = (const float*)d_in[5];
    const float* bv = (const float*)d_in[6];
    float* out = (float*)d_out;

    float *gq, *gk, *gvT, *gs, *ginv;
    cudaGetSymbolAddress((void**)&gq,   g_q);
    cudaGetSymbolAddress((void**)&gk,   g_k);
    cudaGetSymbolAddress((void**)&gvT,  g_vT);
    cudaGetSymbolAddress((void**)&gs,   g_s);
    cudaGetSymbolAddress((void**)&ginv, g_inv);

    // tf32-rounded copies of x and the weights, aliased into g_s (not yet
    // live; g_s is first written by the scores GEMM, which runs after QKV).
    float* xr  = gs;                                   // 8192*1024
    float* wqr = gs + (size_t)MQK * D;                 // 3*1024*1024 contiguous
    float* wkr = wqr + (size_t)D * D;
    float* wvr = wkr + (size_t)D * D;

    // GEMM variants
    auto kQK   = gemm_mma_kernel<false, true,  false, false>;   // Q,K proj
    auto kVT   = gemm_mma_kernel<true,  true,  false, false>;   // V proj, transposed
    auto kEXP  = gemm_mma_kernel<false, true,  true,  false>;   // scores -> E
    auto kPV   = gemm_mma_kernel<false, false, false, true>;    // PV + row scale
    cudaFuncSetAttribute(kQK,  cudaFuncAttributeMaxDynamicSharedMemorySize, DYN_SMEM);
    cudaFuncSetAttribute(kVT,  cudaFuncAttributeMaxDynamicSharedMemorySize, DYN_SMEM);
    cudaFuncSetAttribute(kEXP, cudaFuncAttributeMaxDynamicSharedMemorySize, DYN_SMEM);
    cudaFuncSetAttribute(kPV,  cudaFuncAttributeMaxDynamicSharedMemorySize, DYN_SMEM);

    // 0) prep: round x, Wq, Wk, Wv into gmem scratch. One launch.
    prep_kernel<<<PREP_BLOCKS, 256>>>(x, Wq, Wk, Wv, xr, wqr);

    const dim3 blk(128);

    // 1) Q, K projections: [8192,1024] = xr @ W^T + b (NT, rounded output)
    {
        const dim3 grid(D / BN, MQK / BM, 1);
        kQK<<<grid, blk, DYN_SMEM>>>(xr, D, 0, wqr, D, 0, gq, D, 0,
                                     bq, nullptr, 0, D, 1.0f);
        kQK<<<grid, blk, DYN_SMEM>>>(xr, D, 0, wkr, D, 0, gk, D, 0,
                                     bk, nullptr, 0, D, 1.0f);
    }
    // 1b) V projection, stored transposed via smem-staged epilogue
    {
        const dim3 grid(D / BN, S / BM, Bsz);
        kVT<<<grid, blk, DYN_SMEM>>>(xr,  D, (long long)S * D,
                                     wvr, D, 0,
                                     gvT, S, (long long)D * S,
                                     bv, nullptr, 0, D, 1.0f);
    }

    // 2) E[b] = exp(Q[b] @ K[b]^T / sqrt(D))   (max-free; scores are bounded)
    {
        const dim3 grid(S / BN, S / BM, Bsz);
        kEXP<<<grid, blk, DYN_SMEM>>>(gq, D, (long long)S * D,
                                      gk, D, (long long)S * D,
                                      gs, S, (long long)S * S,
                                      nullptr, nullptr, 0, D,
                                      0.03125f /* 1/sqrt(1024) */);
    }

    // 3) inv rowsum of E
    rowsum_inv_kernel<<<MQK, 256>>>(gs, ginv, S);

    // 4) out[b] = (E[b] @ V[b]) * inv_rowsum[b]  (NT path vs vT)
    {
        const dim3 grid(D / BN, S / BM, Bsz);
        kPV<<<grid, blk, DYN_SMEM>>>(gs,  S, (long long)S * S,
                                     gvT, S, (long long)D * S,
                                     out, D, (long long)S * D,
                                     nullptr, ginv, S, S, 1.0f);
    }
}

// round 11
// speedup vs baseline: 1.0864x; 1.0767x over previous
#include <cuda_runtime.h>
#include <cstdint>

// ---------------------------------------------------------------------------
// SelfAttention: out = softmax((xWq^T+bq)(xWk^T+bk)^T / sqrt(D)) (xWv^T+bv)
// B=4, S=2048, D=1024. fp32 I/O.
// Round 10: structural launch reshaping (mainloop frozen at R3 config):
//   - Q+K merged into ONE N=2048 GEMM (contiguous Wq|Wk, concat bias)
//   - PV split-K x2 (two K=1024 halves -> fp32 partials -> combine kernel
//     that also applies the softmax row normalization)
//   - kept from R9: fused exp epilogue, read-only inv-rowsum, smem-staged
//     transposed V epilogue
// TF32 mma.sync, operands pre-rounded in gmem.
// ---------------------------------------------------------------------------

#define DEV_INLINE __device__ __forceinline__

static constexpr int Bsz = 4;
static constexpr int S   = 2048;
static constexpr int D   = 1024;
static constexpr int MQK = Bsz * S;
static constexpr int N2  = 2 * D;             // merged Q|K width

// Scratch (static __device__ arrays: allocation-free per harness rules)
__device__ float g_qk [(size_t)MQK * N2];     // Q|K fused output (64MB)
__device__ float g_vT [(size_t)Bsz * D * S];  // V stored transposed (32MB)
__device__ float g_s  [(size_t)Bsz * S * S];  // E = exp(scores) (64MB);
                                              // prologue aliases xr/wr here
__device__ float g_p  [(size_t)2 * Bsz * S * D]; // PV split-K partials (64MB)
__device__ float g_b  [3 * D];                // concat bias bq|bk|bv
__device__ float g_inv[MQK];                  // 1 / rowsum(E)

DEV_INLINE float tf32_round(float x) {
    uint32_t u;
    asm("cvt.rna.tf32.f32 %0, %1;" : "=r"(u) : "f"(x));
    return __uint_as_float(u);
}

DEV_INLINE uint32_t smem_u32(const void* p) {
    uint32_t a;
    asm("{ .reg .u64 t; cvta.to.shared.u64 t, %1; cvt.u32.u64 %0, t; }"
        : "=r"(a) : "l"(p));
    return a;
}

DEV_INLINE void cp_async16(uint32_t dst, const void* src) {
    asm volatile("cp.async.cg.shared.global [%0], [%1], 16;"
                 :: "r"(dst), "l"(src) : "memory");
}
DEV_INLINE void cp_commit() {
    asm volatile("cp.async.commit_group;" ::: "memory");
}
template <int N> DEV_INLINE void cp_wait() {
    asm volatile("cp.async.wait_group %0;" :: "n"(N) : "memory");
}

DEV_INLINE void mma_16x8x8(float acc[4], const uint32_t a[4], const uint32_t b[2]) {
    asm volatile(
        "mma.sync.aligned.m16n8k8.row.col.f32.tf32.tf32.f32 "
        "{%0,%1,%2,%3}, {%4,%5,%6,%7}, {%8,%9}, {%0,%1,%2,%3};\n"
        : "+f"(acc[0]), "+f"(acc[1]), "+f"(acc[2]), "+f"(acc[3])
        : "r"(a[0]), "r"(a[1]), "r"(a[2]), "r"(a[3]),
          "r"(b[0]), "r"(b[1]));
}

// ---------------------------------------------------------------------------
// prep_kernel: one launch:
//   blocks [0, 8192)           : xr = tf32_round(x)
//   blocks [8192, 11264)       : wr = tf32_round(Wq|Wk|Wv) contiguous
//   blocks [11264, 11267)      : g_b = bq|bk|bv (copy, fp32 exact)
// ---------------------------------------------------------------------------
static constexpr int PREP_XB = MQK * D / 4 / 256;        // 8192
static constexpr int PREP_WB = D * D / 4 / 256;          // 1024
static constexpr int PREP_BLOCKS = PREP_XB + 3 * PREP_WB + 3;

__global__ void __launch_bounds__(256)
prep_kernel(const float* __restrict__ x,
            const float* __restrict__ Wq, const float* __restrict__ Wk,
            const float* __restrict__ Wv,
            const float* __restrict__ bq, const float* __restrict__ bk,
            const float* __restrict__ bv,
            float* __restrict__ xr, float* __restrict__ wr,
            float* __restrict__ br)
{
    const int b = blockIdx.x;
    const int t = threadIdx.x;
    if (b < PREP_XB) {
        const int i = b * 256 + t;
        float4 v = reinterpret_cast<const float4*>(x)[i];
        v.x = tf32_round(v.x); v.y = tf32_round(v.y);
        v.z = tf32_round(v.z); v.w = tf32_round(v.w);
        reinterpret_cast<float4*>(xr)[i] = v;
    } else if (b < PREP_XB + 3 * PREP_WB) {
        const int wi = b - PREP_XB;
        const int w  = wi >> 10;                 // 0,1,2
        const int i  = (wi & 1023) * 256 + t;
        const float* src = (w == 0) ? Wq : (w == 1) ? Wk : Wv;
        float* dst = wr + (size_t)w * D * D;
        float4 v = reinterpret_cast<const float4*>(src)[i];
        v.x = tf32_round(v.x); v.y = tf32_round(v.y);
        v.z = tf32_round(v.z); v.w = tf32_round(v.w);
        reinterpret_cast<float4*>(dst)[i] = v;
    } else {
        const int w = b - PREP_XB - 3 * PREP_WB; // 0,1,2
        const float* src = (w == 0) ? bq : (w == 1) ? bk : bv;
        reinterpret_cast<float4*>(br + w * D)[t] =
            reinterpret_cast<const float4*>(src)[t];
    }
}

// ---------------------------------------------------------------------------
// TF32 NT GEMM: C[m,n] = alpha * sum_k A[m,k]*B[n,k]  (+bias[n])
// A: [M,K] row-major, B: [N,K] row-major, both ALREADY tf32-valued in gmem.
// CTA 128x128x(BK=32), 128 threads = 4 warps of 64x64.
// Mainloop = frozen R3 config: issue next loads -> cp_wait<1> -> bar ->
// compute -> bar. Epilogue/addressing variants:
//   STORE_T  : smem-staged transpose, coalesced stores of C^T
//   ROUND_OUT: tf32-round before store
//   EXP_OUT  : v = exp(acc*alpha)  (max-free softmax numerator)
//   SPLITK   : bz = batch*2 + half; A,B advance by half*K elements along k
// ---------------------------------------------------------------------------
static constexpr int BM = 128, BN = 128, BK = 32;
static constexpr int ROWF  = BK + 4;             // 36 floats/row (16B-aligned)
static constexpr int STG   = BM * ROWF;          // floats per operand stage
static constexpr int DYN_SMEM = 4 * STG * 4;     // 2 stages x (A+B) = 73728 B
static constexpr int TPS = 132;                  // transpose stage row stride
// transpose stage needs 128*132*4 = 67584 <= 73728 bytes: fits in DYN_SMEM

template <bool STORE_T, bool ROUND_OUT, bool EXP_OUT, bool SPLITK>
__global__ void __launch_bounds__(128)
gemm_mma_kernel(const float* __restrict__ A, int lda, long long strideA,
                const float* __restrict__ B, int ldb, long long strideB,
                float* __restrict__ C, int ldc, long long strideC,
                const float* __restrict__ bias,
                int K, float alpha)
{
    extern __shared__ float dyn[];
    float* As = dyn;                 // [2][STG]
    float* Bs = dyn + 2 * STG;       // [2][STG]
    const uint32_t sA = smem_u32(As);
    const uint32_t sB = smem_u32(Bs);

    const int tid  = threadIdx.x;
    const int wid  = tid >> 5;
    const int lane = tid & 31;
    const int m_w  = (wid & 1) * 64;          // 2 warps along M
    const int n_w  = (wid >> 1) * 64;         // 2 warps along N
    const int group = lane >> 2;              // 0..7
    const int tig   = lane & 3;               // 0..3

    const int bz = blockIdx.z;
    const int bb = SPLITK ? (bz >> 1) : bz;   // batch index
    const int hh = SPLITK ? (bz & 1)  : 0;    // k-half index
    A += (size_t)bb * strideA + (size_t)hh * K;
    B += (size_t)bb * strideB + (size_t)hh * K;
    C += (size_t)bz * strideC;
    const int bm = blockIdx.y * BM;
    const int bn = blockIdx.x * BN;

    float acc[4][8][4];
    #pragma unroll
    for (int mi = 0; mi < 4; mi++)
        #pragma unroll
        for (int ni = 0; ni < 8; ni++)
            #pragma unroll
            for (int r = 0; r < 4; r++) acc[mi][ni][r] = 0.0f;

    // loader: 8 float4 per operand per thread (128 rows x 8 float4-cols)
    const int lr = tid >> 3;           // base row 0..15
    const int lc = tid & 7;            // float4 col 0..7
    auto load_stage = [&](int s, int k0) {
        const uint32_t offA = sA + (uint32_t)s * STG * 4;
        const uint32_t offB = sB + (uint32_t)s * STG * 4;
        #pragma unroll
        for (int i = 0; i < 8; i++) {
            const int r = lr + 16 * i;
            cp_async16(offA + (uint32_t)(r * ROWF + lc * 4) * 4,
                       &A[(size_t)(bm + r) * lda + k0 + lc * 4]);
        }
        #pragma unroll
        for (int i = 0; i < 8; i++) {
            const int r = lr + 16 * i;
            cp_async16(offB + (uint32_t)(r * ROWF + lc * 4) * 4,
                       &B[(size_t)(bn + r) * ldb + k0 + lc * 4]);
        }
        cp_commit();
    };

    const int nst = K / BK;
    load_stage(0, 0);

    for (int i = 0; i < nst; i++) {
        if (i + 1 < nst) {
            load_stage((i + 1) & 1, (i + 1) * BK);
            cp_wait<1>();
        } else {
            cp_wait<0>();
        }
        __syncthreads();

        const float* as = As + (i & 1) * STG;
        const float* bs = Bs + (i & 1) * STG;

        #pragma unroll
        for (int ks = 0; ks < BK; ks += 8) {
            uint32_t afr[4][4];
            #pragma unroll
            for (int mi = 0; mi < 4; mi++) {
                const int r = m_w + mi * 16;
                afr[mi][0] = __float_as_uint(as[(r + group    ) * ROWF + ks + tig    ]);
                afr[mi][1] = __float_as_uint(as[(r + group + 8) * ROWF + ks + tig    ]);
                afr[mi][2] = __float_as_uint(as[(r + group    ) * ROWF + ks + tig + 4]);
                afr[mi][3] = __float_as_uint(as[(r + group + 8) * ROWF + ks + tig + 4]);
            }
            uint32_t bfr[8][2];
            #pragma unroll
            for (int ni = 0; ni < 8; ni++) {
                const int c = n_w + ni * 8;
                bfr[ni][0] = __float_as_uint(bs[(c + group) * ROWF + ks + tig    ]);
                bfr[ni][1] = __float_as_uint(bs[(c + group) * ROWF + ks + tig + 4]);
            }
            #pragma unroll
            for (int mi = 0; mi < 4; mi++)
                #pragma unroll
                for (int ni = 0; ni < 8; ni++)
                    mma_16x8x8(acc[mi][ni], afr[mi], bfr[ni]);
        }
        __syncthreads();
    }

    // ---- epilogue ----
    #pragma unroll
    for (int mi = 0; mi < 4; mi++) {
        const int rloc0 = m_w + mi * 16 + group;
        const int row0  = bm + rloc0;
        #pragma unroll
        for (int ni = 0; ni < 8; ni++) {
            const int cloc0 = n_w + ni * 8 + tig * 2;
            const int col0  = bn + cloc0;
            float v00 = acc[mi][ni][0] * alpha;
            float v01 = acc[mi][ni][1] * alpha;
            float v10 = acc[mi][ni][2] * alpha;
            float v11 = acc[mi][ni][3] * alpha;
            if (bias) {
                const float b0 = bias[col0], b1 = bias[col0 + 1];
                v00 += b0; v01 += b1; v10 += b0; v11 += b1;
            }
            if (EXP_OUT) {
                v00 = __expf(v00); v01 = __expf(v01);
                v10 = __expf(v10); v11 = __expf(v11);
            }
            if (ROUND_OUT) {
                v00 = tf32_round(v00); v01 = tf32_round(v01);
                v10 = tf32_round(v10); v11 = tf32_round(v11);
            }
            if (!STORE_T) {
                *reinterpret_cast<float2*>(&C[(size_t)row0 * ldc + col0]) =
                    make_float2(v00, v01);
                *reinterpret_cast<float2*>(&C[(size_t)(row0 + 8) * ldc + col0]) =
                    make_float2(v10, v11);
            } else {
                // stage into smem transpose buffer: T[c][r], stride TPS
                dyn[(size_t)cloc0 * TPS + rloc0]           = v00;
                dyn[(size_t)(cloc0 + 1) * TPS + rloc0]     = v01;
                dyn[(size_t)cloc0 * TPS + rloc0 + 8]       = v10;
                dyn[(size_t)(cloc0 + 1) * TPS + rloc0 + 8] = v11;
            }
        }
    }

    if (STORE_T) {
        __syncthreads();
        // each warp writes 32 transposed rows, coalesced float4
        #pragma unroll
        for (int j = 0; j < 32; j++) {
            const int dr = wid * 32 + j;
            const float4 v = *reinterpret_cast<const float4*>(
                &dyn[(size_t)dr * TPS + lane * 4]);
            *reinterpret_cast<float4*>(
                &C[(size_t)(bn + dr) * ldc + bm + lane * 4]) = v;
        }
    }
}

// ---------------------------------------------------------------------------
// inv-rowsum reduction: g_inv[row] = 1 / sum(E[row, :]).
// One block (256 threads) per row of 2048 floats. Read-only over E.
// ---------------------------------------------------------------------------
__global__ void __launch_bounds__(256)
rowsum_inv_kernel(const float* __restrict__ E, float* __restrict__ inv, int ncols)
{
    const float4* p = reinterpret_cast<const float4*>(E + (size_t)blockIdx.x * ncols);
    const int tid  = threadIdx.x;
    const int warp = tid >> 5;
    const int lane = tid & 31;

    __shared__ float red[8];

    float sum = 0.f;
    #pragma unroll
    for (int i = 0; i < 2; i++) {
        const float4 v = p[tid + 256 * i];
        sum += (v.x + v.y) + (v.z + v.w);
    }
    #pragma unroll
    for (int o = 16; o > 0; o >>= 1)
        sum += __shfl_xor_sync(0xffffffffu, sum, o);
    if (lane == 0) red[warp] = sum;
    __syncthreads();
    if (tid == 0) {
        float total = 0.f;
        #pragma unroll
        for (int w = 0; w < 8; w++) total += red[w];
        inv[blockIdx.x] = 1.0f / total;
    }
}

// ---------------------------------------------------------------------------
// combine: out[r][:] = (p[2b][sr][:] + p[2b+1][sr][:]) * inv[r]
// One block (256 threads) per output row r (1024 floats = 256 float4).
// ---------------------------------------------------------------------------
__global__ void __launch_bounds__(256)
combine_kernel(const float* __restrict__ p, const float* __restrict__ inv,
               float* __restrict__ out)
{
    const int r  = blockIdx.x;          // 0..8191
    const int t  = threadIdx.x;
    const int b  = r >> 11;             // batch (2048 rows each)
    const int sr = r & 2047;
    const float4* a0 = reinterpret_cast<const float4*>(
        p + ((size_t)(2 * b)     * S + sr) * D);
    const float4* a1 = reinterpret_cast<const float4*>(
        p + ((size_t)(2 * b + 1) * S + sr) * D);
    const float s = inv[r];
    const float4 u = a0[t];
    const float4 v = a1[t];
    float4 o;
    o.x = (u.x + v.x) * s;  o.y = (u.y + v.y) * s;
    o.z = (u.z + v.z) * s;  o.w = (u.w + v.w) * s;
    reinterpret_cast<float4*>(out + (size_t)r * D)[t] = o;
}

// ---------------------------------------------------------------------------
extern "C" void kernel_launch(void* const* d_in, const int* in_sizes, int n_in,
                              void* d_out, int out_size)
{
    const float* x  = (const float*)d_in[0];
    const float* Wq = (const float*)d_in[1];
    const float* bq = (const float*)d_in[2];
    const float* Wk = (const float*)d_in[3];
    const float* bk = (const float*)d_in[4];
    const float* Wv = (const float*)d_in[5];
    const float* bv = (const float*)d_in[6];
    float* out = (float*)d_out;

    float *gqk, *gvT, *gs, *gp, *gb, *ginv;
    cudaGetSymbolAddress((void**)&gqk,  g_qk);
    cudaGetSymbolAddress((void**)&gvT,  g_vT);
    cudaGetSymbolAddress((void**)&gs,   g_s);
    cudaGetSymbolAddress((void**)&gp,   g_p);
    cudaGetSymbolAddress((void**)&gb,   g_b);
    cudaGetSymbolAddress((void**)&ginv, g_inv);

    // tf32-rounded copies of x and weights, aliased into g_s (not yet live;
    // g_s is first written by the scores GEMM, which runs after projections).
    float* xr = gs;                                    // 8192*1024
    float* wr = gs + (size_t)MQK * D;                  // 3*1024*1024 contiguous

    // GEMM variants
    auto kQK  = gemm_mma_kernel<false, true,  false, false>;  // merged Q|K proj
    auto kVT  = gemm_mma_kernel<true,  true,  false, false>;  // V proj, transposed
    auto kEXP = gemm_mma_kernel<false, true,  true,  false>;  // scores -> E
    auto kPV  = gemm_mma_kernel<false, false, false, true>;   // PV split-K halves
    cudaFuncSetAttribute(kQK,  cudaFuncAttributeMaxDynamicSharedMemorySize, DYN_SMEM);
    cudaFuncSetAttribute(kVT,  cudaFuncAttributeMaxDynamicSharedMemorySize, DYN_SMEM);
    cudaFuncSetAttribute(kEXP, cudaFuncAttributeMaxDynamicSharedMemorySize, DYN_SMEM);
    cudaFuncSetAttribute(kPV,  cudaFuncAttributeMaxDynamicSharedMemorySize, DYN_SMEM);

    // 0) prep: round x + weights (contiguous Wq|Wk|Wv), concat bias. One launch.
    prep_kernel<<<PREP_BLOCKS, 256>>>(x, Wq, Wk, Wv, bq, bk, bv, xr, wr, gb);

    const dim3 blk(128);

    // 1) merged Q|K projection: [8192, 2048] = xr @ (Wq|Wk)^T + (bq|bk)
    {
        const dim3 grid(N2 / BN, MQK / BM, 1);
        kQK<<<grid, blk, DYN_SMEM>>>(xr, D, 0, wr, D, 0, gqk, N2, 0,
                                     gb, D, 1.0f);
    }
    // 1b) V projection, stored transposed via smem-staged epilogue
    {
        const dim3 grid(D / BN, S / BM, Bsz);
        kVT<<<grid, blk, DYN_SMEM>>>(xr,  D, (long long)S * D,
                                     wr + (size_t)2 * D * D, D, 0,
                                     gvT, S, (long long)D * S,
                                     gb + 2 * D, D, 1.0f);
    }

    // 2) E[b] = exp(Q[b] @ K[b]^T / sqrt(D))   (Q, K = column halves of g_qk)
    {
        const dim3 grid(S / BN, S / BM, Bsz);
        kEXP<<<grid, blk, DYN_SMEM>>>(gqk,     N2, (long long)S * N2,
                                      gqk + D, N2, (long long)S * N2,
                                      gs, S, (long long)S * S,
                                      nullptr, D, 0.03125f /* 1/sqrt(1024) */);
    }

    // 3) inv rowsum of E
    rowsum_inv_kernel<<<MQK, 256>>>(gs, ginv, S);

    // 4) PV split-K x2: partial[b*2+h] = E[b][:, hK:] @ vT[b][:, hK:]^T
    {
        const dim3 grid(D / BN, S / BM, Bsz * 2);
        kPV<<<grid, blk, DYN_SMEM>>>(gs,  S, (long long)S * S,
                                     gvT, S, (long long)D * S,
                                     gp,  D, (long long)S * D,
                                     nullptr, S / 2, 1.0f);
    }

    // 5) combine halves + apply softmax normalization
    combine_kernel<<<MQK, 256>>>(gp, ginv, out);
}

// round 12
// speedup vs baseline: 1.1229x; 1.0335x over previous
#include <cuda_runtime.h>
#include <cstdint>

// ---------------------------------------------------------------------------
// SelfAttention: out = softmax((xWq^T+bq)(xWk^T+bk)^T / sqrt(D)) (xWv^T+bv)
// B=4, S=2048, D=1024. fp32 I/O.
// Round 11: R10 design (merged Q|K, PV split-K x2, fused exp, rowsum,
// smem-staged V transpose) + ONE change: __launch_bounds__(128, 3) on the
// GEMM to cap regs at 170 and restore the 3rd resident CTA/SM (the R10
// profile showed the EXP kernel at 171 regs = one register over the
// 3-CTA register-file cliff at 170.6).
// TF32 mma.sync, operands pre-rounded in gmem.
// ---------------------------------------------------------------------------

#define DEV_INLINE __device__ __forceinline__

static constexpr int Bsz = 4;
static constexpr int S   = 2048;
static constexpr int D   = 1024;
static constexpr int MQK = Bsz * S;
static constexpr int N2  = 2 * D;             // merged Q|K width

// Scratch (static __device__ arrays: allocation-free per harness rules)
__device__ float g_qk [(size_t)MQK * N2];     // Q|K fused output (64MB)
__device__ float g_vT [(size_t)Bsz * D * S];  // V stored transposed (32MB)
__device__ float g_s  [(size_t)Bsz * S * S];  // E = exp(scores) (64MB);
                                              // prologue aliases xr/wr here
__device__ float g_p  [(size_t)2 * Bsz * S * D]; // PV split-K partials (64MB)
__device__ float g_b  [3 * D];                // concat bias bq|bk|bv
__device__ float g_inv[MQK];                  // 1 / rowsum(E)

DEV_INLINE float tf32_round(float x) {
    uint32_t u;
    asm("cvt.rna.tf32.f32 %0, %1;" : "=r"(u) : "f"(x));
    return __uint_as_float(u);
}

DEV_INLINE uint32_t smem_u32(const void* p) {
    uint32_t a;
    asm("{ .reg .u64 t; cvta.to.shared.u64 t, %1; cvt.u32.u64 %0, t; }"
        : "=r"(a) : "l"(p));
    return a;
}

DEV_INLINE void cp_async16(uint32_t dst, const void* src) {
    asm volatile("cp.async.cg.shared.global [%0], [%1], 16;"
                 :: "r"(dst), "l"(src) : "memory");
}
DEV_INLINE void cp_commit() {
    asm volatile("cp.async.commit_group;" ::: "memory");
}
template <int N> DEV_INLINE void cp_wait() {
    asm volatile("cp.async.wait_group %0;" :: "n"(N) : "memory");
}

DEV_INLINE void mma_16x8x8(float acc[4], const uint32_t a[4], const uint32_t b[2]) {
    asm volatile(
        "mma.sync.aligned.m16n8k8.row.col.f32.tf32.tf32.f32 "
        "{%0,%1,%2,%3}, {%4,%5,%6,%7}, {%8,%9}, {%0,%1,%2,%3};\n"
        : "+f"(acc[0]), "+f"(acc[1]), "+f"(acc[2]), "+f"(acc[3])
        : "r"(a[0]), "r"(a[1]), "r"(a[2]), "r"(a[3]),
          "r"(b[0]), "r"(b[1]));
}

// ---------------------------------------------------------------------------
// prep_kernel: one launch:
//   blocks [0, 8192)           : xr = tf32_round(x)
//   blocks [8192, 11264)       : wr = tf32_round(Wq|Wk|Wv) contiguous
//   blocks [11264, 11267)      : g_b = bq|bk|bv (copy, fp32 exact)
// ---------------------------------------------------------------------------
static constexpr int PREP_XB = MQK * D / 4 / 256;        // 8192
static constexpr int PREP_WB = D * D / 4 / 256;          // 1024
static constexpr int PREP_BLOCKS = PREP_XB + 3 * PREP_WB + 3;

__global__ void __launch_bounds__(256)
prep_kernel(const float* __restrict__ x,
            const float* __restrict__ Wq, const float* __restrict__ Wk,
            const float* __restrict__ Wv,
            const float* __restrict__ bq, const float* __restrict__ bk,
            const float* __restrict__ bv,
            float* __restrict__ xr, float* __restrict__ wr,
            float* __restrict__ br)
{
    const int b = blockIdx.x;
    const int t = threadIdx.x;
    if (b < PREP_XB) {
        const int i = b * 256 + t;
        float4 v = reinterpret_cast<const float4*>(x)[i];
        v.x = tf32_round(v.x); v.y = tf32_round(v.y);
        v.z = tf32_round(v.z); v.w = tf32_round(v.w);
        reinterpret_cast<float4*>(xr)[i] = v;
    } else if (b < PREP_XB + 3 * PREP_WB) {
        const int wi = b - PREP_XB;
        const int w  = wi >> 10;                 // 0,1,2
        const int i  = (wi & 1023) * 256 + t;
        const float* src = (w == 0) ? Wq : (w == 1) ? Wk : Wv;
        float* dst = wr + (size_t)w * D * D;
        float4 v = reinterpret_cast<const float4*>(src)[i];
        v.x = tf32_round(v.x); v.y = tf32_round(v.y);
        v.z = tf32_round(v.z); v.w = tf32_round(v.w);
        reinterpret_cast<float4*>(dst)[i] = v;
    } else {
        const int w = b - PREP_XB - 3 * PREP_WB; // 0,1,2
        const float* src = (w == 0) ? bq : (w == 1) ? bk : bv;
        reinterpret_cast<float4*>(br + w * D)[t] =
            reinterpret_cast<const float4*>(src)[t];
    }
}

// ---------------------------------------------------------------------------
// TF32 NT GEMM: C[m,n] = alpha * sum_k A[m,k]*B[n,k]  (+bias[n])
// A: [M,K] row-major, B: [N,K] row-major, both ALREADY tf32-valued in gmem.
// CTA 128x128x(BK=32), 128 threads = 4 warps of 64x64.
// __launch_bounds__(128, 3): cap regs at 170 so 3 CTAs/SM fit (RF cliff).
// Mainloop = frozen R3 config: issue next loads -> cp_wait<1> -> bar ->
// compute -> bar. Epilogue/addressing variants:
//   STORE_T  : smem-staged transpose, coalesced stores of C^T
//   ROUND_OUT: tf32-round before store
//   EXP_OUT  : v = exp(acc*alpha)  (max-free softmax numerator)
//   SPLITK   : bz = batch*2 + half; A,B advance by half*K elements along k
// ---------------------------------------------------------------------------
static constexpr int BM = 128, BN = 128, BK = 32;
static constexpr int ROWF  = BK + 4;             // 36 floats/row (16B-aligned)
static constexpr int STG   = BM * ROWF;          // floats per operand stage
static constexpr int DYN_SMEM = 4 * STG * 4;     // 2 stages x (A+B) = 73728 B
static constexpr int TPS = 132;                  // transpose stage row stride
// transpose stage needs 128*132*4 = 67584 <= 73728 bytes: fits in DYN_SMEM
// 3 CTAs x 73728 = 221184 B <= 228KB/SM: smem allows 3 CTAs.

template <bool STORE_T, bool ROUND_OUT, bool EXP_OUT, bool SPLITK>
__global__ void __launch_bounds__(128, 3)
gemm_mma_kernel(const float* __restrict__ A, int lda, long long strideA,
                const float* __restrict__ B, int ldb, long long strideB,
                float* __restrict__ C, int ldc, long long strideC,
                const float* __restrict__ bias,
                int K, float alpha)
{
    extern __shared__ float dyn[];
    float* As = dyn;                 // [2][STG]
    float* Bs = dyn + 2 * STG;       // [2][STG]
    const uint32_t sA = smem_u32(As);
    const uint32_t sB = smem_u32(Bs);

    const int tid  = threadIdx.x;
    const int wid  = tid >> 5;
    const int lane = tid & 31;
    const int m_w  = (wid & 1) * 64;          // 2 warps along M
    const int n_w  = (wid >> 1) * 64;         // 2 warps along N
    const int group = lane >> 2;              // 0..7
    const int tig   = lane & 3;               // 0..3

    const int bz = blockIdx.z;
    const int bb = SPLITK ? (bz >> 1) : bz;   // batch index
    const int hh = SPLITK ? (bz & 1)  : 0;    // k-half index
    A += (size_t)bb * strideA + (size_t)hh * K;
    B += (size_t)bb * strideB + (size_t)hh * K;
    C += (size_t)bz * strideC;
    const int bm = blockIdx.y * BM;
    const int bn = blockIdx.x * BN;

    float acc[4][8][4];
    #pragma unroll
    for (int mi = 0; mi < 4; mi++)
        #pragma unroll
        for (int ni = 0; ni < 8; ni++)
            #pragma unroll
            for (int r = 0; r < 4; r++) acc[mi][ni][r] = 0.0f;

    // loader: 8 float4 per operand per thread (128 rows x 8 float4-cols)
    const int lr = tid >> 3;           // base row 0..15
    const int lc = tid & 7;            // float4 col 0..7
    auto load_stage = [&](int s, int k0) {
        const uint32_t offA = sA + (uint32_t)s * STG * 4;
        const uint32_t offB = sB + (uint32_t)s * STG * 4;
        #pragma unroll
        for (int i = 0; i < 8; i++) {
            const int r = lr + 16 * i;
            cp_async16(offA + (uint32_t)(r * ROWF + lc * 4) * 4,
                       &A[(size_t)(bm + r) * lda + k0 + lc * 4]);
        }
        #pragma unroll
        for (int i = 0; i < 8; i++) {
            const int r = lr + 16 * i;
            cp_async16(offB + (uint32_t)(r * ROWF + lc * 4) * 4,
                       &B[(size_t)(bn + r) * ldb + k0 + lc * 4]);
        }
        cp_commit();
    };

    const int nst = K / BK;
    load_stage(0, 0);

    for (int i = 0; i < nst; i++) {
        if (i + 1 < nst) {
            load_stage((i + 1) & 1, (i + 1) * BK);
            cp_wait<1>();
        } else {
            cp_wait<0>();
        }
        __syncthreads();

        const float* as = As + (i & 1) * STG;
        const float* bs = Bs + (i & 1) * STG;

        #pragma unroll
        for (int ks = 0; ks < BK; ks += 8) {
            uint32_t afr[4][4];
            #pragma unroll
            for (int mi = 0; mi < 4; mi++) {
                const int r = m_w + mi * 16;
                afr[mi][0] = __float_as_uint(as[(r + group    ) * ROWF + ks + tig    ]);
                afr[mi][1] = __float_as_uint(as[(r + group + 8) * ROWF + ks + tig    ]);
                afr[mi][2] = __float_as_uint(as[(r + group    ) * ROWF + ks + tig + 4]);
                afr[mi][3] = __float_as_uint(as[(r + group + 8) * ROWF + ks + tig + 4]);
            }
            uint32_t bfr[8][2];
            #pragma unroll
            for (int ni = 0; ni < 8; ni++) {
                const int c = n_w + ni * 8;
                bfr[ni][0] = __float_as_uint(bs[(c + group) * ROWF + ks + tig    ]);
                bfr[ni][1] = __float_as_uint(bs[(c + group) * ROWF + ks + tig + 4]);
            }
            #pragma unroll
            for (int mi = 0; mi < 4; mi++)
                #pragma unroll
                for (int ni = 0; ni < 8; ni++)
                    mma_16x8x8(acc[mi][ni], afr[mi], bfr[ni]);
        }
        __syncthreads();
    }

    // ---- epilogue ----
    #pragma unroll
    for (int mi = 0; mi < 4; mi++) {
        const int rloc0 = m_w + mi * 16 + group;
        const int row0  = bm + rloc0;
        #pragma unroll
        for (int ni = 0; ni < 8; ni++) {
            const int cloc0 = n_w + ni * 8 + tig * 2;
            const int col0  = bn + cloc0;
            float v00 = acc[mi][ni][0] * alpha;
            float v01 = acc[mi][ni][1] * alpha;
            float v10 = acc[mi][ni][2] * alpha;
            float v11 = acc[mi][ni][3] * alpha;
            if (bias) {
                const float b0 = bias[col0], b1 = bias[col0 + 1];
                v00 += b0; v01 += b1; v10 += b0; v11 += b1;
            }
            if (EXP_OUT) {
                v00 = __expf(v00); v01 = __expf(v01);
                v10 = __expf(v10); v11 = __expf(v11);
            }
            if (ROUND_OUT) {
                v00 = tf32_round(v00); v01 = tf32_round(v01);
                v10 = tf32_round(v10); v11 = tf32_round(v11);
            }
            if (!STORE_T) {
                *reinterpret_cast<float2*>(&C[(size_t)row0 * ldc + col0]) =
                    make_float2(v00, v01);
                *reinterpret_cast<float2*>(&C[(size_t)(row0 + 8) * ldc + col0]) =
                    make_float2(v10, v11);
            } else {
                // stage into smem transpose buffer: T[c][r], stride TPS
                dyn[(size_t)cloc0 * TPS + rloc0]           = v00;
                dyn[(size_t)(cloc0 + 1) * TPS + rloc0]     = v01;
                dyn[(size_t)cloc0 * TPS + rloc0 + 8]       = v10;
                dyn[(size_t)(cloc0 + 1) * TPS + rloc0 + 8] = v11;
            }
        }
    }

    if (STORE_T) {
        __syncthreads();
        // each warp writes 32 transposed rows, coalesced float4
        #pragma unroll
        for (int j = 0; j < 32; j++) {
            const int dr = wid * 32 + j;
            const float4 v = *reinterpret_cast<const float4*>(
                &dyn[(size_t)dr * TPS + lane * 4]);
            *reinterpret_cast<float4*>(
                &C[(size_t)(bn + dr) * ldc + bm + lane * 4]) = v;
        }
    }
}

// ---------------------------------------------------------------------------
// inv-rowsum reduction: g_inv[row] = 1 / sum(E[row, :]).
// One block (256 threads) per row of 2048 floats. Read-only over E.
// ---------------------------------------------------------------------------
__global__ void __launch_bounds__(256)
rowsum_inv_kernel(const float* __restrict__ E, float* __restrict__ inv, int ncols)
{
    const float4* p = reinterpret_cast<const float4*>(E + (size_t)blockIdx.x * ncols);
    const int tid  = threadIdx.x;
    const int warp = tid >> 5;
    const int lane = tid & 31;

    __shared__ float red[8];

    float sum = 0.f;
    #pragma unroll
    for (int i = 0; i < 2; i++) {
        const float4 v = p[tid + 256 * i];
        sum += (v.x + v.y) + (v.z + v.w);
    }
    #pragma unroll
    for (int o = 16; o > 0; o >>= 1)
        sum += __shfl_xor_sync(0xffffffffu, sum, o);
    if (lane == 0) red[warp] = sum;
    __syncthreads();
    if (tid == 0) {
        float total = 0.f;
        #pragma unroll
        for (int w = 0; w < 8; w++) total += red[w];
        inv[blockIdx.x] = 1.0f / total;
    }
}

// ---------------------------------------------------------------------------
// combine: out[r][:] = (p[2b][sr][:] + p[2b+1][sr][:]) * inv[r]
// One block (256 threads) per output row r (1024 floats = 256 float4).
// ---------------------------------------------------------------------------
__global__ void __launch_bounds__(256)
combine_kernel(const float* __restrict__ p, const float* __restrict__ inv,
               float* __restrict__ out)
{
    const int r  = blockIdx.x;          // 0..8191
    const int t  = threadIdx.x;
    const int b  = r >> 11;             // batch (2048 rows each)
    const int sr = r & 2047;
    const float4* a0 = reinterpret_cast<const float4*>(
        p + ((size_t)(2 * b)     * S + sr) * D);
    const float4* a1 = reinterpret_cast<const float4*>(
        p + ((size_t)(2 * b + 1) * S + sr) * D);
    const float s = inv[r];
    const float4 u = a0[t];
    const float4 v = a1[t];
    float4 o;
    o.x = (u.x + v.x) * s;  o.y = (u.y + v.y) * s;
    o.z = (u.z + v.z) * s;  o.w = (u.w + v.w) * s;
    reinterpret_cast<float4*>(out + (size_t)r * D)[t] = o;
}

// ---------------------------------------------------------------------------
extern "C" void kernel_launch(void* const* d_in, const int* in_sizes, int n_in,
                              void* d_out, int out_size)
{
    const float* x  = (const float*)d_in[0];
    const float* Wq = (const float*)d_in[1];
    const float* bq = (const float*)d_in[2];
    const float* Wk = (const float*)d_in[3];
    const float* bk = (const float*)d_in[4];
    const float* Wv = (const float*)d_in[5];
    const float* bv = (const float*)d_in[6];
    float* out = (float*)d_out;

    float *gqk, *gvT, *gs, *gp, *gb, *ginv;
    cudaGetSymbolAddress((void**)&gqk,  g_qk);
    cudaGetSymbolAddress((void**)&gvT,  g_vT);
    cudaGetSymbolAddress((void**)&gs,   g_s);
    cudaGetSymbolAddress((void**)&gp,   g_p);
    cudaGetSymbolAddress((void**)&gb,   g_b);
    cudaGetSymbolAddress((void**)&ginv, g_inv);

    // tf32-rounded copies of x and weights, aliased into g_s (not yet live;
    // g_s is first written by the scores GEMM, which runs after projections).
    float* xr = gs;                                    // 8192*1024
    float* wr = gs + (size_t)MQK * D;                  // 3*1024*1024 contiguous

    // GEMM variants
    auto kQK  = gemm_mma_kernel<false, true,  false, false>;  // merged Q|K proj
    auto kVT  = gemm_mma_kernel<true,  true,  false, false>;  // V proj, transposed
    auto kEXP = gemm_mma_kernel<false, true,  true,  false>;  // scores -> E
    auto kPV  = gemm_mma_kernel<false, false, false, true>;   // PV split-K halves
    cudaFuncSetAttribute(kQK,  cudaFuncAttributeMaxDynamicSharedMemorySize, DYN_SMEM);
    cudaFuncSetAttribute(kVT,  cudaFuncAttributeMaxDynamicSharedMemorySize, DYN_SMEM);
    cudaFuncSetAttribute(kEXP, cudaFuncAttributeMaxDynamicSharedMemorySize, DYN_SMEM);
    cudaFuncSetAttribute(kPV,  cudaFuncAttributeMaxDynamicSharedMemorySize, DYN_SMEM);

    // 0) prep: round x + weights (contiguous Wq|Wk|Wv), concat bias. One launch.
    prep_kernel<<<PREP_BLOCKS, 256>>>(x, Wq, Wk, Wv, bq, bk, bv, xr, wr, gb);

    const dim3 blk(128);

    // 1) merged Q|K projection: [8192, 2048] = xr @ (Wq|Wk)^T + (bq|bk)
    {
        const dim3 grid(N2 / BN, MQK / BM, 1);
        kQK<<<grid, blk, DYN_SMEM>>>(xr, D, 0, wr, D, 0, gqk, N2, 0,
                                     gb, D, 1.0f);
    }
    // 1b) V projection, stored transposed via smem-staged epilogue
    {
        const dim3 grid(D / BN, S / BM, Bsz);
        kVT<<<grid, blk, DYN_SMEM>>>(xr,  D, (long long)S * D,
                                     wr + (size_t)2 * D * D, D, 0,
                                     gvT, S, (long long)D * S,
                                     gb + 2 * D, D, 1.0f);
    }

    // 2) E[b] = exp(Q[b] @ K[b]^T / sqrt(D))   (Q, K = column halves of g_qk)
    {
        const dim3 grid(S / BN, S / BM, Bsz);
        kEXP<<<grid, blk, DYN_SMEM>>>(gqk,     N2, (long long)S * N2,
                                      gqk + D, N2, (long long)S * N2,
                                      gs, S, (long long)S * S,
                                      nullptr, D, 0.03125f /* 1/sqrt(1024) */);
    }

    // 3) inv rowsum of E
    rowsum_inv_kernel<<<MQK, 256>>>(gs, ginv, S);

    // 4) PV split-K x2: partial[b*2+h] = E[b][:, hK:] @ vT[b][:, hK:]^T
    {
        const dim3 grid(D / BN, S / BM, Bsz * 2);
        kPV<<<grid, blk, DYN_SMEM>>>(gs,  S, (long long)S * S,
                                     gvT, S, (long long)D * S,
                                     gp,  D, (long long)S * D,
                                     nullptr, S / 2, 1.0f);
    }

    // 5) combine halves + apply softmax normalization
    combine_kernel<<<MQK, 256>>>(gp, ginv, out);
}

// round 13
// speedup vs baseline: 1.1377x; 1.0132x over previous
#include <cuda_runtime.h>
#include <cstdint>

// ---------------------------------------------------------------------------
// SelfAttention: out = softmax((xWq^T+bq)(xWk^T+bk)^T / sqrt(D)) (xWv^T+bv)
// B=4, S=2048, D=1024. fp32 I/O.
// Round 12: fully fused QKV projection in ONE 1536-CTA launch (4 waves vs 5):
// Q|K columns store normally into g_qk; V columns (bn>=2048) store transposed
// into g_vT via the verified smem-staged epilogue. No extra kernels/traffic.
// Kept from R11: __launch_bounds__(128,3) (3 CTAs/SM), fused exp epilogue,
// read-only inv-rowsum, PV split-K x2 + combine. TF32 mma.sync, operands
// pre-rounded in gmem. Mainloop frozen at the R3 config.
// ---------------------------------------------------------------------------

#define DEV_INLINE __device__ __forceinline__

static constexpr int Bsz = 4;
static constexpr int S   = 2048;
static constexpr int D   = 1024;
static constexpr int MQK = Bsz * S;
static constexpr int N2  = 2 * D;             // Q|K width (g_qk row stride)
static constexpr int N3  = 3 * D;             // fused QKV width

// Scratch (static __device__ arrays: allocation-free per harness rules)
__device__ float g_qk [(size_t)MQK * N2];     // Q|K output (64MB)
__device__ float g_vT [(size_t)Bsz * D * S];  // V stored transposed (32MB)
__device__ float g_s  [(size_t)Bsz * S * S];  // E = exp(scores) (64MB);
                                              // prologue aliases xr/wr here
__device__ float g_p  [(size_t)2 * Bsz * S * D]; // PV split-K partials (64MB)
__device__ float g_b  [N3];                   // concat bias bq|bk|bv
__device__ float g_inv[MQK];                  // 1 / rowsum(E)

DEV_INLINE float tf32_round(float x) {
    uint32_t u;
    asm("cvt.rna.tf32.f32 %0, %1;" : "=r"(u) : "f"(x));
    return __uint_as_float(u);
}

DEV_INLINE uint32_t smem_u32(const void* p) {
    uint32_t a;
    asm("{ .reg .u64 t; cvta.to.shared.u64 t, %1; cvt.u32.u64 %0, t; }"
        : "=r"(a) : "l"(p));
    return a;
}

DEV_INLINE void cp_async16(uint32_t dst, const void* src) {
    asm volatile("cp.async.cg.shared.global [%0], [%1], 16;"
                 :: "r"(dst), "l"(src) : "memory");
}
DEV_INLINE void cp_commit() {
    asm volatile("cp.async.commit_group;" ::: "memory");
}
template <int N> DEV_INLINE void cp_wait() {
    asm volatile("cp.async.wait_group %0;" :: "n"(N) : "memory");
}

DEV_INLINE void mma_16x8x8(float acc[4], const uint32_t a[4], const uint32_t b[2]) {
    asm volatile(
        "mma.sync.aligned.m16n8k8.row.col.f32.tf32.tf32.f32 "
        "{%0,%1,%2,%3}, {%4,%5,%6,%7}, {%8,%9}, {%0,%1,%2,%3};\n"
        : "+f"(acc[0]), "+f"(acc[1]), "+f"(acc[2]), "+f"(acc[3])
        : "r"(a[0]), "r"(a[1]), "r"(a[2]), "r"(a[3]),
          "r"(b[0]), "r"(b[1]));
}

// ---------------------------------------------------------------------------
// prep_kernel: one launch:
//   blocks [0, 8192)           : xr = tf32_round(x)
//   blocks [8192, 11264)       : wr = tf32_round(Wq|Wk|Wv) contiguous
//   blocks [11264, 11267)      : g_b = bq|bk|bv (copy, fp32 exact)
// ---------------------------------------------------------------------------
static constexpr int PREP_XB = MQK * D / 4 / 256;        // 8192
static constexpr int PREP_WB = D * D / 4 / 256;          // 1024
static constexpr int PREP_BLOCKS = PREP_XB + 3 * PREP_WB + 3;

__global__ void __launch_bounds__(256)
prep_kernel(const float* __restrict__ x,
            const float* __restrict__ Wq, const float* __restrict__ Wk,
            const float* __restrict__ Wv,
            const float* __restrict__ bq, const float* __restrict__ bk,
            const float* __restrict__ bv,
            float* __restrict__ xr, float* __restrict__ wr,
            float* __restrict__ br)
{
    const int b = blockIdx.x;
    const int t = threadIdx.x;
    if (b < PREP_XB) {
        const int i = b * 256 + t;
        float4 v = reinterpret_cast<const float4*>(x)[i];
        v.x = tf32_round(v.x); v.y = tf32_round(v.y);
        v.z = tf32_round(v.z); v.w = tf32_round(v.w);
        reinterpret_cast<float4*>(xr)[i] = v;
    } else if (b < PREP_XB + 3 * PREP_WB) {
        const int wi = b - PREP_XB;
        const int w  = wi >> 10;                 // 0,1,2
        const int i  = (wi & 1023) * 256 + t;
        const float* src = (w == 0) ? Wq : (w == 1) ? Wk : Wv;
        float* dst = wr + (size_t)w * D * D;
        float4 v = reinterpret_cast<const float4*>(src)[i];
        v.x = tf32_round(v.x); v.y = tf32_round(v.y);
        v.z = tf32_round(v.z); v.w = tf32_round(v.w);
        reinterpret_cast<float4*>(dst)[i] = v;
    } else {
        const int w = b - PREP_XB - 3 * PREP_WB; // 0,1,2
        const float* src = (w == 0) ? bq : (w == 1) ? bk : bv;
        reinterpret_cast<float4*>(br + w * D)[t] =
            reinterpret_cast<const float4*>(src)[t];
    }
}

// ---------------------------------------------------------------------------
// TF32 NT GEMM: C[m,n] = alpha * sum_k A[m,k]*B[n,k]  (+bias[n])
// A: [M,K] row-major, B: [N,K] row-major, both ALREADY tf32-valued in gmem.
// CTA 128x128x(BK=32), 128 threads = 4 warps of 64x64.
// __launch_bounds__(128, 3): cap regs at 170 so 3 CTAs/SM fit (RF cliff).
// Mainloop = frozen R3 config. Variants:
//   FUSE_V   : CTAs with bn >= N2 write their tile TRANSPOSED into vtC
//              (per-batch V^T); others store normally into C (ldc = N2).
//   ROUND_OUT: tf32-round before store
//   EXP_OUT  : v = exp(acc*alpha)  (max-free softmax numerator)
//   SPLITK   : bz = batch*2 + half; A,B advance by half*K elements along k
// ---------------------------------------------------------------------------
static constexpr int BM = 128, BN = 128, BK = 32;
static constexpr int ROWF  = BK + 4;             // 36 floats/row (16B-aligned)
static constexpr int STG   = BM * ROWF;          // floats per operand stage
static constexpr int DYN_SMEM = 4 * STG * 4;     // 2 stages x (A+B) = 73728 B
static constexpr int TPS = 132;                  // transpose stage row stride
// transpose stage needs 128*132*4 = 67584 <= 73728 bytes: fits in DYN_SMEM
// 3 CTAs x 73728 = 221184 B <= 228KB/SM: smem allows 3 CTAs.

template <bool FUSE_V, bool ROUND_OUT, bool EXP_OUT, bool SPLITK>
__global__ void __launch_bounds__(128, 3)
gemm_mma_kernel(const float* __restrict__ A, int lda, long long strideA,
                const float* __restrict__ B, int ldb, long long strideB,
                float* __restrict__ C, int ldc, long long strideC,
                float* __restrict__ vtC,
                const float* __restrict__ bias,
                int K, float alpha)
{
    extern __shared__ float dyn[];
    float* As = dyn;                 // [2][STG]
    float* Bs = dyn + 2 * STG;       // [2][STG]
    const uint32_t sA = smem_u32(As);
    const uint32_t sB = smem_u32(Bs);

    const int tid  = threadIdx.x;
    const int wid  = tid >> 5;
    const int lane = tid & 31;
    const int m_w  = (wid & 1) * 64;          // 2 warps along M
    const int n_w  = (wid >> 1) * 64;         // 2 warps along N
    const int group = lane >> 2;              // 0..7
    const int tig   = lane & 3;               // 0..3

    const int bz = blockIdx.z;
    const int bb = SPLITK ? (bz >> 1) : bz;   // batch index
    const int hh = SPLITK ? (bz & 1)  : 0;    // k-half index
    A += (size_t)bb * strideA + (size_t)hh * K;
    B += (size_t)bb * strideB + (size_t)hh * K;
    C += (size_t)bz * strideC;
    const int bm = blockIdx.y * BM;
    const int bn = blockIdx.x * BN;

    float acc[4][8][4];
    #pragma unroll
    for (int mi = 0; mi < 4; mi++)
        #pragma unroll
        for (int ni = 0; ni < 8; ni++)
            #pragma unroll
            for (int r = 0; r < 4; r++) acc[mi][ni][r] = 0.0f;

    // loader: 8 float4 per operand per thread (128 rows x 8 float4-cols)
    const int lr = tid >> 3;           // base row 0..15
    const int lc = tid & 7;            // float4 col 0..7
    auto load_stage = [&](int s, int k0) {
        const uint32_t offA = sA + (uint32_t)s * STG * 4;
        const uint32_t offB = sB + (uint32_t)s * STG * 4;
        #pragma unroll
        for (int i = 0; i < 8; i++) {
            const int r = lr + 16 * i;
            cp_async16(offA + (uint32_t)(r * ROWF + lc * 4) * 4,
                       &A[(size_t)(bm + r) * lda + k0 + lc * 4]);
        }
        #pragma unroll
        for (int i = 0; i < 8; i++) {
            const int r = lr + 16 * i;
            cp_async16(offB + (uint32_t)(r * ROWF + lc * 4) * 4,
                       &B[(size_t)(bn + r) * ldb + k0 + lc * 4]);
        }
        cp_commit();
    };

    const int nst = K / BK;
    load_stage(0, 0);

    for (int i = 0; i < nst; i++) {
        if (i + 1 < nst) {
            load_stage((i + 1) & 1, (i + 1) * BK);
            cp_wait<1>();
        } else {
            cp_wait<0>();
        }
        __syncthreads();

        const float* as = As + (i & 1) * STG;
        const float* bs = Bs + (i & 1) * STG;

        #pragma unroll
        for (int ks = 0; ks < BK; ks += 8) {
            uint32_t afr[4][4];
            #pragma unroll
            for (int mi = 0; mi < 4; mi++) {
                const int r = m_w + mi * 16;
                afr[mi][0] = __float_as_uint(as[(r + group    ) * ROWF + ks + tig    ]);
                afr[mi][1] = __float_as_uint(as[(r + group + 8) * ROWF + ks + tig    ]);
                afr[mi][2] = __float_as_uint(as[(r + group    ) * ROWF + ks + tig + 4]);
                afr[mi][3] = __float_as_uint(as[(r + group + 8) * ROWF + ks + tig + 4]);
            }
            uint32_t bfr[8][2];
            #pragma unroll
            for (int ni = 0; ni < 8; ni++) {
                const int c = n_w + ni * 8;
                bfr[ni][0] = __float_as_uint(bs[(c + group) * ROWF + ks + tig    ]);
                bfr[ni][1] = __float_as_uint(bs[(c + group) * ROWF + ks + tig + 4]);
            }
            #pragma unroll
            for (int mi = 0; mi < 4; mi++)
                #pragma unroll
                for (int ni = 0; ni < 8; ni++)
                    mma_16x8x8(acc[mi][ni], afr[mi], bfr[ni]);
        }
        __syncthreads();
    }

    // ---- epilogue ----
    const bool v_block = FUSE_V && (bn >= N2);

    #pragma unroll
    for (int mi = 0; mi < 4; mi++) {
        const int rloc0 = m_w + mi * 16 + group;
        const int row0  = bm + rloc0;
        #pragma unroll
        for (int ni = 0; ni < 8; ni++) {
            const int cloc0 = n_w + ni * 8 + tig * 2;
            const int col0  = bn + cloc0;
            float v00 = acc[mi][ni][0] * alpha;
            float v01 = acc[mi][ni][1] * alpha;
            float v10 = acc[mi][ni][2] * alpha;
            float v11 = acc[mi][ni][3] * alpha;
            if (bias) {
                const float b0 = bias[col0], b1 = bias[col0 + 1];
                v00 += b0; v01 += b1; v10 += b0; v11 += b1;
            }
            if (EXP_OUT) {
                v00 = __expf(v00); v01 = __expf(v01);
                v10 = __expf(v10); v11 = __expf(v11);
            }
            if (ROUND_OUT) {
                v00 = tf32_round(v00); v01 = tf32_round(v01);
                v10 = tf32_round(v10); v11 = tf32_round(v11);
            }
            if (!FUSE_V) {
                *reinterpret_cast<float2*>(&C[(size_t)row0 * ldc + col0]) =
                    make_float2(v00, v01);
                *reinterpret_cast<float2*>(&C[(size_t)(row0 + 8) * ldc + col0]) =
                    make_float2(v10, v11);
            } else if (!v_block) {
                *reinterpret_cast<float2*>(&C[(size_t)row0 * ldc + col0]) =
                    make_float2(v00, v01);
                *reinterpret_cast<float2*>(&C[(size_t)(row0 + 8) * ldc + col0]) =
                    make_float2(v10, v11);
            } else {
                // stage into smem transpose buffer: T[c][r], stride TPS
                dyn[(size_t)cloc0 * TPS + rloc0]           = v00;
                dyn[(size_t)(cloc0 + 1) * TPS + rloc0]     = v01;
                dyn[(size_t)cloc0 * TPS + rloc0 + 8]       = v10;
                dyn[(size_t)(cloc0 + 1) * TPS + rloc0 + 8] = v11;
            }
        }
    }

    if (FUSE_V) {
        if (v_block) {
            __syncthreads();
            // V tile: rows bm..bm+127 lie inside one batch (BM | S)
            const int vb  = bm >> 11;          // batch = bm / S
            const int sm0 = bm & (S - 1);      // seq offset within batch
            const int d0  = bn - N2;           // head-dim offset
            float* vt = vtC + (size_t)vb * D * S;
            // each warp writes 32 transposed rows, coalesced float4
            #pragma unroll
            for (int j = 0; j < 32; j++) {
                const int dr = wid * 32 + j;
                const float4 v = *reinterpret_cast<const float4*>(
                    &dyn[(size_t)dr * TPS + lane * 4]);
                *reinterpret_cast<float4*>(
                    &vt[(size_t)(d0 + dr) * S + sm0 + lane * 4]) = v;
            }
        }
    }
}

// ---------------------------------------------------------------------------
// inv-rowsum reduction: g_inv[row] = 1 / sum(E[row, :]).
// One block (256 threads) per row of 2048 floats. Read-only over E.
// ---------------------------------------------------------------------------
__global__ void __launch_bounds__(256)
rowsum_inv_kernel(const float* __restrict__ E, float* __restrict__ inv, int ncols)
{
    const float4* p = reinterpret_cast<const float4*>(E + (size_t)blockIdx.x * ncols);
    const int tid  = threadIdx.x;
    const int warp = tid >> 5;
    const int lane = tid & 31;

    __shared__ float red[8];

    float sum = 0.f;
    #pragma unroll
    for (int i = 0; i < 2; i++) {
        const float4 v = p[tid + 256 * i];
        sum += (v.x + v.y) + (v.z + v.w);
    }
    #pragma unroll
    for (int o = 16; o > 0; o >>= 1)
        sum += __shfl_xor_sync(0xffffffffu, sum, o);
    if (lane == 0) red[warp] = sum;
    __syncthreads();
    if (tid == 0) {
        float total = 0.f;
        #pragma unroll
        for (int w = 0; w < 8; w++) total += red[w];
        inv[blockIdx.x] = 1.0f / total;
    }
}

// ---------------------------------------------------------------------------
// combine: out[r][:] = (p[2b][sr][:] + p[2b+1][sr][:]) * inv[r]
// One block (256 threads) per output row r (1024 floats = 256 float4).
// ---------------------------------------------------------------------------
__global__ void __launch_bounds__(256)
combine_kernel(const float* __restrict__ p, const float* __restrict__ inv,
               float* __restrict__ out)
{
    const int r  = blockIdx.x;          // 0..8191
    const int t  = threadIdx.x;
    const int b  = r >> 11;             // batch (2048 rows each)
    const int sr = r & 2047;
    const float4* a0 = reinterpret_cast<const float4*>(
        p + ((size_t)(2 * b)     * S + sr) * D);
    const float4* a1 = reinterpret_cast<const float4*>(
        p + ((size_t)(2 * b + 1) * S + sr) * D);
    const float s = inv[r];
    const float4 u = a0[t];
    const float4 v = a1[t];
    float4 o;
    o.x = (u.x + v.x) * s;  o.y = (u.y + v.y) * s;
    o.z = (u.z + v.z) * s;  o.w = (u.w + v.w) * s;
    reinterpret_cast<float4*>(out + (size_t)r * D)[t] = o;
}

// ---------------------------------------------------------------------------
extern "C" void kernel_launch(void* const* d_in, const int* in_sizes, int n_in,
                              void* d_out, int out_size)
{
    const float* x  = (const float*)d_in[0];
    const float* Wq = (const float*)d_in[1];
    const float* bq = (const float*)d_in[2];
    const float* Wk = (const float*)d_in[3];
    const float* bk = (const float*)d_in[4];
    const float* Wv = (const float*)d_in[5];
    const float* bv = (const float*)d_in[6];
    float* out = (float*)d_out;

    float *gqk, *gvT, *gs, *gp, *gb, *ginv;
    cudaGetSymbolAddress((void**)&gqk,  g_qk);
    cudaGetSymbolAddress((void**)&gvT,  g_vT);
    cudaGetSymbolAddress((void**)&gs,   g_s);
    cudaGetSymbolAddress((void**)&gp,   g_p);
    cudaGetSymbolAddress((void**)&gb,   g_b);
    cudaGetSymbolAddress((void**)&ginv, g_inv);

    // tf32-rounded copies of x and weights, aliased into g_s (not yet live;
    // g_s is first written by the scores GEMM, which runs after projections).
    float* xr = gs;                                    // 8192*1024
    float* wr = gs + (size_t)MQK * D;                  // 3*1024*1024 contiguous

    // GEMM variants
    auto kQKV = gemm_mma_kernel<true,  true,  false, false>;  // fused QKV proj
    auto kEXP = gemm_mma_kernel<false, true,  true,  false>;  // scores -> E
    auto kPV  = gemm_mma_kernel<false, false, false, true>;   // PV split-K halves
    cudaFuncSetAttribute(kQKV, cudaFuncAttributeMaxDynamicSharedMemorySize, DYN_SMEM);
    cudaFuncSetAttribute(kEXP, cudaFuncAttributeMaxDynamicSharedMemorySize, DYN_SMEM);
    cudaFuncSetAttribute(kPV,  cudaFuncAttributeMaxDynamicSharedMemorySize, DYN_SMEM);

    // 0) prep: round x + weights (contiguous Wq|Wk|Wv), concat bias. One launch.
    prep_kernel<<<PREP_BLOCKS, 256>>>(x, Wq, Wk, Wv, bq, bk, bv, xr, wr, gb);

    const dim3 blk(128);

    // 1) fused QKV projection, ONE launch (1536 CTAs = 4 waves):
    //    cols [0,2048): Q|K -> g_qk (ldc = N2)
    //    cols [2048,3072): V -> g_vT transposed (per batch)
    {
        const dim3 grid(N3 / BN, MQK / BM, 1);
        kQKV<<<grid, blk, DYN_SMEM>>>(xr, D, 0, wr, D, 0, gqk, N2, 0,
                                      gvT, gb, D, 1.0f);
    }

    // 2) E[b] = exp(Q[b] @ K[b]^T / sqrt(D))   (Q, K = column halves of g_qk)
    {
        const dim3 grid(S / BN, S / BM, Bsz);
        kEXP<<<grid, blk, DYN_SMEM>>>(gqk,     N2, (long long)S * N2,
                                      gqk + D, N2, (long long)S * N2,
                                      gs, S, (long long)S * S,
                                      nullptr, nullptr, D,
                                      0.03125f /* 1/sqrt(1024) */);
    }

    // 3) inv rowsum of E
    rowsum_inv_kernel<<<MQK, 256>>>(gs, ginv, S);

    // 4) PV split-K x2: partial[b*2+h] = E[b][:, hK:] @ vT[b][:, hK:]^T
    {
        const dim3 grid(D / BN, S / BM, Bsz * 2);
        kPV<<<grid, blk, DYN_SMEM>>>(gs,  S, (long long)S * S,
                                     gvT, S, (long long)D * S,
                                     gp,  D, (long long)S * D,
                                     nullptr, nullptr, S / 2, 1.0f);
    }

    // 5) combine halves + apply softmax normalization
    combine_kernel<<<MQK, 256>>>(gp, ginv, out);
}